// round 16
// baseline (speedup 1.0000x reference)
#include <cuda_runtime.h>
#include <math.h>

#define TT    256    // t-rows per block tile
#define CT    32     // channels per block tile
#define HALO  56     // max conv radius
#define ROWS  (TT + 2*HALO)   // 368
#define ROWSP 372    // padded column stride (mult of 4 for LDS.128 alignment)
#define NTHREADS 256
#define NTY   8      // t-groups per block
#define RCHUNK 4     // outputs per thread per chunk
#define WSF   (CT * ROWSP)    // float offset of weights in smem (16B aligned)

typedef unsigned long long ull;

// ---------------- packed f32x2 helpers ----------------
__device__ __forceinline__ ull ffma2(ull a, ull b, ull c) {
    ull d; asm("fma.rn.f32x2 %0,%1,%2,%3;" : "=l"(d) : "l"(a), "l"(b), "l"(c)); return d;
}
__device__ __forceinline__ ull fmul2(ull a, ull b) {
    ull d; asm("mul.rn.f32x2 %0,%1,%2;" : "=l"(d) : "l"(a), "l"(b)); return d;
}
__device__ __forceinline__ ull pk2(float lo, float hi) {
    ull d; asm("mov.b64 %0,{%1,%2};" : "=l"(d) : "f"(lo), "f"(hi)); return d;
}
__device__ __forceinline__ void upk2(ull a, float& lo, float& hi) {
    asm("mov.b64 {%0,%1},%2;" : "=f"(lo), "=f"(hi) : "l"(a));
}
__device__ __forceinline__ float rcpf(float x) {
    float r; asm("rcp.approx.f32 %0,%1;" : "=f"(r) : "f"(x)); return r;
}
__device__ __forceinline__ float ex2f(float x) {
    float r; asm("ex2.approx.f32 %0,%1;" : "=f"(r) : "f"(x)); return r;
}
__device__ __forceinline__ float tanhf_a(float x) {
    float r; asm("tanh.approx.f32 %0,%1;" : "=f"(r) : "f"(x)); return r;
}
// a + b as FFMA-imm (imm multiplier 1.0, exact)
__device__ __forceinline__ float fadd1(float a, float b) {
    float r; asm("fma.rn.f32 %0,%1,0f3F800000,%2;" : "=f"(r) : "f"(a), "f"(b)); return r;
}
// c - a as FFMA-imm (imm multiplier -1.0, exact)
__device__ __forceinline__ float fnma1(float a, float c) {
    float r; asm("fma.rn.f32 %0,%1,0fBF800000,%2;" : "=f"(r) : "f"(a), "f"(c)); return r;
}

// ---------------- compile-time Gaussian bank ----------------
__host__ __device__ constexpr double cexp_(double x) {
    double y = x / 256.0;
    double s = 1.0, term = 1.0;
    for (int n = 1; n <= 24; ++n) { term = term * y / (double)n; s += term; }
    for (int i = 0; i < 8; ++i) s = s * s;
    return s;
}

struct BankT { float w[5][113]; };

__host__ __device__ constexpr BankT make_bank() {
    BankT b{};
    double sig[5] = {2.5, 4.0, 6.0, 9.0, 14.0};
    for (int k = 0; k < 5; ++k) {
        double s = sig[k];
        int r = (int)(4.0 * s);          // 10,16,24,36,56
        double sum = 0.0;
        for (int d = -r; d <= r; ++d) sum += cexp_(-0.5 * ((double)d / s) * ((double)d / s));
        for (int d = -r; d <= r; ++d)
            b.w[k][56 + d] = (float)(cexp_(-0.5 * ((double)d / s) * ((double)d / s)) / sum);
    }
    return b;
}

// ---------------- kernel ----------------
__global__ void __launch_bounds__(NTHREADS, 3)
agt_kernel(const float* __restrict__ x, const float* __restrict__ W1,
           const float* __restrict__ b1, const float* __restrict__ W2,
           const float* __restrict__ b2, float* __restrict__ out,
           int B, int T, int C)
{
    constexpr BankT BANK = make_bank();
    constexpr int RAD[5] = {10, 16, 24, 36, 56};

    extern __shared__ float sm[];
    float* S   = sm;               // transposed tile: S[cc*ROWSP + r]
    float* ws2 = sm + WSF;         // weights: 32 j-blocks of 16 floats + b2d(8)

    const int tx  = threadIdx.x;           // channel in tile (0..31) = lane
    const int ty  = threadIdx.y;           // t-group (0..7) = warp id
    const int tid = ty * CT + tx;
    const int c0  = blockIdx.x * CT;
    const int t0  = blockIdx.y * TT;
    const int bb  = blockIdx.z;

    // --- stage weights: per-j 16-float blocks, each value duplicated (lo,hi):
    // block j: [W1m | W1v | W1x | b1 | W2d0 | W2d1 | W2d2 | W2d3] (8 pairs)
    // then b2d: 4 pairs at float offset 512.
    // 4-logit softmax: W2d[j][k] = (W2[j][k]-W2[j][4]) * 0.5*log2(e),
    //                  b2d[k]    = (b2[k]-b2[4]) * log2(e);   e4 == 1.
    for (int i = tid; i < 520; i += NTHREADS) {
        float v;
        if (i < 512) {
            int j = i >> 4, pr = (i >> 1) & 7;
            if      (pr < 3)  v = W1[pr * 32 + j];
            else if (pr == 3) v = b1[j];
            else {
                int k = pr - 4;
                v = (W2[j * 5 + k] - W2[j * 5 + 4]) * (0.5f * 1.4426950408889634f);
            }
        } else {
            int k = (i - 512) >> 1;
            v = (b2[k] - b2[4]) * 1.4426950408889634f;
        }
        ws2[i] = v;
    }

    // --- stage x tile TRANSPOSED (zero padded outside [0,T)) ---
    const float* xb = x + ((size_t)bb * T) * C + c0;
    for (int idx = tid; idx < ROWS * CT; idx += NTHREADS) {
        int r  = idx >> 5;          // row
        int cc = idx & (CT - 1);    // channel (lane) -> coalesced gmem read
        int g  = t0 - HALO + r;
        float v = 0.0f;
        if (g >= 0 && g < T) v = xb[(size_t)g * C + cc];
        S[cc * ROWSP + r] = v;
    }
    __syncthreads();

    const float* colp = S + tx * ROWSP;    // this thread's channel column
    const ull*   wp   = (const ull*)ws2;

    // tanh-GELU: u = z*(CK1 + CK2*z^2)
    const ull CK1 = pk2(0.7978845608f, 0.7978845608f);
    const ull CK2 = pk2(0.0356774081f, 0.0356774081f);

    const bool interior = (t0 >= 8) && (t0 + TT + 8 <= T);
    const int  lb0 = ty * (TT / NTY);      // first local output row of this warp
    const int  tb0 = t0 + lb0;

    // ---- carried sliding sums: init window of virtual output (tb0-1)
    // rows lb0+HALO-8 .. lb0+HALO+7 : lb0+48 is mult of 4 -> 4 float4 loads
    float s = 0.0f, s2 = 0.0f;
    if (interior) {
        #pragma unroll
        for (int q = 0; q < 4; ++q) {
            const float4 iv = *(const float4*)&colp[lb0 + HALO - 8 + 4 * q];
            s  = fadd1(iv.x, fadd1(iv.y, fadd1(iv.z, fadd1(iv.w, s))));
            s2 = fmaf(iv.x, iv.x, s2);
            s2 = fmaf(iv.y, iv.y, s2);
            s2 = fmaf(iv.z, iv.z, s2);
            s2 = fmaf(iv.w, iv.w, s2);
        }
    } else {
        #pragma unroll
        for (int u = -8; u <= 7; ++u) {
            int g = tb0 + u;
            g = (g < 0)  ? -g              : g;
            g = (g >= T) ? (2 * T - 2 - g) : g;
            float w = colp[g - t0 + HALO];
            s  = fadd1(w, s);
            s2 = fmaf(w, w, s2);
        }
    }

    #pragma unroll 1
    for (int chunk = 0; chunk < TT / (NTY * RCHUNK); ++chunk) {   // 8 iterations
        const int lb = lb0 + chunk * RCHUNK;   // local first output row
        const int tb = t0 + lb;                // global first output row
        const int b0 = lb + HALO;              // tile row of output 0 (b0 % 4 == 0)

        // center taps (also xv): rows b0..b0+3, 16B aligned
        const float4 cq = *(const float4*)&colp[b0];
        const float cqa[4] = {cq.x, cq.y, cq.z, cq.w};

        // ---------- phase 1: carried mean / var (float4 adds/removes) ----------
        float m[RCHUNK], va[RCHUNK];
        if (interior) {
            const float4 aq = *(const float4*)&colp[b0 + 8];   // rows b0+8..b0+11
            const float4 rq = *(const float4*)&colp[b0 - 8];   // rows b0-8..b0-5
            const float wa4[4] = {aq.x, aq.y, aq.z, aq.w};
            const float wr4[4] = {rq.x, rq.y, rq.z, rq.w};
            #pragma unroll
            for (int i = 0; i < RCHUNK; ++i) {
                float wa = wa4[i], wr = wr4[i];
                s  = fadd1(wa, fnma1(wr, s));
                s2 = fmaf(wa, wa, s2);
                s2 = fmaf(wr, -wr, s2);
                float mm  = fmaf(s,  1.0f / 16.0f, 0.0f);
                float m2v = fmaf(s2, 1.0f / 16.0f, 0.0f);
                m[i]  = mm;
                va[i] = fmaxf(fmaf(-mm, mm, m2v), 0.0f);
            }
        } else {
            #pragma unroll
            for (int i = 0; i < RCHUNK; ++i) {
                int ga = tb + i + 8;  ga = (ga >= T) ? (2 * T - 2 - ga) : ga;
                int gr = tb + i - 8;  gr = (gr < 0)  ? -gr              : gr;
                float wa = colp[ga - t0 + HALO];
                float wr = colp[gr - t0 + HALO];
                s  = fadd1(wa, fnma1(wr, s));
                s2 = fmaf(wa, wa, s2);
                s2 = fmaf(wr, -wr, s2);
                float mm  = fmaf(s,  1.0f / 16.0f, 0.0f);
                float m2v = fmaf(s2, 1.0f / 16.0f, 0.0f);
                m[i]  = mm;
                va[i] = fmaxf(fmaf(-mm, mm, m2v), 0.0f);
            }
        }

        // pack features into f32x2 pairs (i, i+1)
        ull m2[2], v2p[2], x2[2];
        #pragma unroll
        for (int p = 0; p < 2; ++p) {
            m2[p]  = pk2(m[2 * p],  m[2 * p + 1]);
            v2p[p] = pk2(va[2 * p], va[2 * p + 1]);
            x2[p]  = pk2(cqa[2 * p], cqa[2 * p + 1]);
        }

        // ---------- init MLP accumulators + conv state ----------
        ull lg[2][4];
        #pragma unroll
        for (int p = 0; p < 2; ++p)
            #pragma unroll
            for (int k = 0; k < 4; ++k) lg[p][k] = wp[256 + k];   // b2d pairs

        float Y[RCHUNK][5];
        #pragma unroll
        for (int o = 0; o < RCHUNK; ++o)
            #pragma unroll
            for (int k = 0; k < 5; ++k) Y[o][k] = fmaf(cqa[o], BANK.w[k][56], 0.0f);
        float Lp[4] = {cqa[0], cqa[1], cqa[2], cqa[3]};
        float Rp[4] = {cqa[0], cqa[1], cqa[2], cqa[3]};

        // ---------- FUSED phase: MLP (latency-chained) + conv (filler FFMAs) ----
        // 16 steps: each = 2 MLP j-blocks; steps 0..13 also run 1 conv group.
        // The independent conv FFMA stream fills the tanh/LDS stall slots.
        #pragma unroll
        for (int st = 0; st < 16; ++st) {
            #pragma unroll
            for (int jj = 0; jj < 2; ++jj) {
                const int j = 2 * st + jj;
                const ull* wj = wp + 8 * j;
                ull w1m = wj[0], w1v = wj[1], w1x = wj[2], bj = wj[3];
                ull w20 = wj[4], w21 = wj[5], w22 = wj[6], w23 = wj[7];
                #pragma unroll
                for (int p = 0; p < 2; ++p) {
                    ull z  = ffma2(m2[p], w1m, ffma2(v2p[p], w1v, ffma2(x2[p], w1x, bj)));
                    ull zz = fmul2(z, z);
                    ull u  = fmul2(z, ffma2(zz, CK2, CK1));
                    float ul, uh; upk2(u, ul, uh);
                    ull th = pk2(tanhf_a(ul), tanhf_a(uh));
                    ull g  = ffma2(z, th, z);        // g' = z*(1+tanh(u)) = 2*gelu
                    lg[p][0] = ffma2(g, w20, lg[p][0]);
                    lg[p][1] = ffma2(g, w21, lg[p][1]);
                    lg[p][2] = ffma2(g, w22, lg[p][2]);
                    lg[p][3] = ffma2(g, w23, lg[p][3]);
                }
            }
            if (st < 14) {
                const float4 lq = *(const float4*)&colp[b0 - 4 * st - 4];
                const float4 rq = *(const float4*)&colp[b0 + 4 * st + 4];
                const float Lc[4] = {lq.x, lq.y, lq.z, lq.w};
                const float Rc[4] = {rq.x, rq.y, rq.z, rq.w};
                #pragma unroll
                for (int dd = 1; dd <= 4; ++dd) {
                    const int d = 4 * st + dd;
                    #pragma unroll
                    for (int o = 0; o < RCHUNK; ++o) {
                        const int el = 4 - dd + o;          // L row b0-d+o
                        const int er = dd + o;              // R row b0+d+o
                        float Lv = (el < 4) ? Lc[el] : Lp[el - 4];
                        float Rv = (er < 4) ? Rp[er] : Rc[er - 4];
                        if (d > RAD[3]) {
                            Y[o][4] = fmaf(Lv, BANK.w[4][56 + d], Y[o][4]);
                            Y[o][4] = fmaf(Rv, BANK.w[4][56 + d], Y[o][4]);
                        } else {
                            float sv = fadd1(Lv, Rv);       // FFMA-imm
                            #pragma unroll
                            for (int k = 0; k < 5; ++k) {
                                if (d <= RAD[k])
                                    Y[o][k] = fmaf(sv, BANK.w[k][56 + d], Y[o][k]);
                            }
                        }
                    }
                }
                #pragma unroll
                for (int e = 0; e < 4; ++e) { Lp[e] = Lc[e]; Rp[e] = Rc[e]; }
            }
        }

        // ---------- softmax (e4 = 1) + mix + store ----------
        float ew[RCHUNK][4];
        #pragma unroll
        for (int p = 0; p < 2; ++p) {
            float lo, hi;
            #pragma unroll
            for (int k = 0; k < 4; ++k) {
                upk2(lg[p][k], lo, hi);
                ew[2 * p][k]     = ex2f(lo);
                ew[2 * p + 1][k] = ex2f(hi);
            }
        }

        float* op = out + ((size_t)bb * T + tb) * C + c0 + tx;
        const float one = 1.0f;
        #pragma unroll
        for (int o = 0; o < RCHUNK; ++o) {
            float e0 = ew[o][0], e1 = ew[o][1], e2 = ew[o][2], e3 = ew[o][3];
            float sum = fadd1(e0, fadd1(e1, fadd1(e2, fadd1(e3, one))));
            float dot = fmaf(e0, Y[o][0], Y[o][4]);
            dot = fmaf(e1, Y[o][1], dot);
            dot = fmaf(e2, Y[o][2], dot);
            dot = fmaf(e3, Y[o][3], dot);
            op[(size_t)o * C] = dot * rcpf(sum);
        }
    }
}

// ---------------- launch ----------------
extern "C" void kernel_launch(void* const* d_in, const int* in_sizes, int n_in,
                              void* d_out, int out_size) {
    const float* x  = (const float*)d_in[0];
    const float* W1 = (const float*)d_in[1];
    const float* b1 = (const float*)d_in[2];
    const float* W2 = (const float*)d_in[3];
    const float* b2 = (const float*)d_in[4];
    float* out = (float*)d_out;

    const int B = 16, T = 4096, C = 256;
    size_t smem = (size_t)(WSF + 576) * sizeof(float);
    cudaFuncSetAttribute(agt_kernel, cudaFuncAttributeMaxDynamicSharedMemorySize, (int)smem);

    dim3 grid(C / CT, T / TT, B);
    dim3 block(CT, NTY);
    agt_kernel<<<grid, block, smem>>>(x, W1, b1, W2, b2, out, B, T, C);
}

// round 17
// speedup vs baseline: 1.2598x; 1.2598x over previous
#include <cuda_runtime.h>
#include <math.h>

#define TT    256    // t-rows per block tile
#define CT    32     // channels per block tile
#define HALO  56     // max conv radius
#define ROWS  (TT + 2*HALO)   // 368
#define ROWSP 372    // padded column stride (mult of 4 for LDS.128 alignment)
#define NTHREADS 256
#define NTY   8      // t-groups per block
#define RCHUNK 4     // outputs per thread per chunk
#define WSF   (CT * ROWSP)    // float offset of weights in smem (16B aligned)

typedef unsigned long long ull;

// ---------------- packed f32x2 helpers ----------------
__device__ __forceinline__ ull ffma2(ull a, ull b, ull c) {
    ull d; asm("fma.rn.f32x2 %0,%1,%2,%3;" : "=l"(d) : "l"(a), "l"(b), "l"(c)); return d;
}
__device__ __forceinline__ ull fmul2(ull a, ull b) {
    ull d; asm("mul.rn.f32x2 %0,%1,%2;" : "=l"(d) : "l"(a), "l"(b)); return d;
}
__device__ __forceinline__ ull pk2(float lo, float hi) {
    ull d; asm("mov.b64 %0,{%1,%2};" : "=l"(d) : "f"(lo), "f"(hi)); return d;
}
__device__ __forceinline__ void upk2(ull a, float& lo, float& hi) {
    asm("mov.b64 {%0,%1},%2;" : "=f"(lo), "=f"(hi) : "l"(a));
}
__device__ __forceinline__ float rcpf(float x) {
    float r; asm("rcp.approx.f32 %0,%1;" : "=f"(r) : "f"(x)); return r;
}
__device__ __forceinline__ float ex2f(float x) {
    float r; asm("ex2.approx.f32 %0,%1;" : "=f"(r) : "f"(x)); return r;
}
__device__ __forceinline__ float tanhf_a(float x) {
    float r; asm("tanh.approx.f32 %0,%1;" : "=f"(r) : "f"(x)); return r;
}
// a + b as FFMA-imm (imm multiplier 1.0, exact)
__device__ __forceinline__ float fadd1(float a, float b) {
    float r; asm("fma.rn.f32 %0,%1,0f3F800000,%2;" : "=f"(r) : "f"(a), "f"(b)); return r;
}
// c - a as FFMA-imm (imm multiplier -1.0, exact)
__device__ __forceinline__ float fnma1(float a, float c) {
    float r; asm("fma.rn.f32 %0,%1,0fBF800000,%2;" : "=f"(r) : "f"(a), "f"(c)); return r;
}

// ---------------- compile-time Gaussian bank ----------------
__host__ __device__ constexpr double cexp_(double x) {
    double y = x / 256.0;
    double s = 1.0, term = 1.0;
    for (int n = 1; n <= 24; ++n) { term = term * y / (double)n; s += term; }
    for (int i = 0; i < 8; ++i) s = s * s;
    return s;
}

struct BankT { float w[5][113]; };

__host__ __device__ constexpr BankT make_bank() {
    BankT b{};
    double sig[5] = {2.5, 4.0, 6.0, 9.0, 14.0};
    for (int k = 0; k < 5; ++k) {
        double s = sig[k];
        int r = (int)(4.0 * s);          // 10,16,24,36,56
        double sum = 0.0;
        for (int d = -r; d <= r; ++d) sum += cexp_(-0.5 * ((double)d / s) * ((double)d / s));
        for (int d = -r; d <= r; ++d)
            b.w[k][56 + d] = (float)(cexp_(-0.5 * ((double)d / s) * ((double)d / s)) / sum);
    }
    return b;
}

// ---------------- kernel ----------------
__global__ void __launch_bounds__(NTHREADS, 4)
agt_kernel(const float* __restrict__ x, const float* __restrict__ W1,
           const float* __restrict__ b1, const float* __restrict__ W2,
           const float* __restrict__ b2, float* __restrict__ out,
           int B, int T, int C)
{
    constexpr BankT BANK = make_bank();
    constexpr int RAD[5] = {10, 16, 24, 36, 56};

    extern __shared__ float sm[];
    float* S   = sm;               // transposed tile: S[cc*ROWSP + r]
    float* ws2 = sm + WSF;         // weights: 32 j-blocks of 16 floats + b2d(8)

    const int tx  = threadIdx.x;           // channel in tile (0..31) = lane
    const int ty  = threadIdx.y;           // t-group (0..7) = warp id
    const int tid = ty * CT + tx;
    const int c0  = blockIdx.x * CT;
    const int t0  = blockIdx.y * TT;
    const int bb  = blockIdx.z;

    // --- stage weights: per-j 16-float blocks, each value duplicated (lo,hi):
    // block j: [W1m | W1v | W1x | b1 | W2d0 | W2d1 | W2d2 | W2d3] (8 pairs)
    // then b2d: 4 pairs at float offset 512.
    // 4-logit softmax: W2d[j][k] = (W2[j][k]-W2[j][4]) * 0.5*log2(e),
    //                  b2d[k]    = (b2[k]-b2[4]) * log2(e);   e4 == 1.
    for (int i = tid; i < 520; i += NTHREADS) {
        float v;
        if (i < 512) {
            int j = i >> 4, pr = (i >> 1) & 7;
            if      (pr < 3)  v = W1[pr * 32 + j];
            else if (pr == 3) v = b1[j];
            else {
                int k = pr - 4;
                v = (W2[j * 5 + k] - W2[j * 5 + 4]) * (0.5f * 1.4426950408889634f);
            }
        } else {
            int k = (i - 512) >> 1;
            v = (b2[k] - b2[4]) * 1.4426950408889634f;
        }
        ws2[i] = v;
    }

    // --- stage x tile TRANSPOSED (zero padded outside [0,T)) ---
    const float* xb = x + ((size_t)bb * T) * C + c0;
    for (int idx = tid; idx < ROWS * CT; idx += NTHREADS) {
        int r  = idx >> 5;          // row
        int cc = idx & (CT - 1);    // channel (lane) -> coalesced gmem read
        int g  = t0 - HALO + r;
        float v = 0.0f;
        if (g >= 0 && g < T) v = xb[(size_t)g * C + cc];
        S[cc * ROWSP + r] = v;
    }
    __syncthreads();

    const float* colp = S + tx * ROWSP;    // this thread's channel column
    const ull*   wp   = (const ull*)ws2;

    // tanh-GELU: u = z*(CK1 + CK2*z^2)
    const ull CK1 = pk2(0.7978845608f, 0.7978845608f);
    const ull CK2 = pk2(0.0356774081f, 0.0356774081f);

    const bool interior = (t0 >= 8) && (t0 + TT + 8 <= T);
    const int  lb0 = ty * (TT / NTY);      // first local output row of this warp
    const int  tb0 = t0 + lb0;

    // ---- carried sliding sums: init window of virtual output (tb0-1)
    // rows lb0+HALO-8 .. lb0+HALO+7 : lb0+48 is mult of 4 -> 4 float4 loads
    float s = 0.0f, s2 = 0.0f;
    if (interior) {
        #pragma unroll
        for (int q = 0; q < 4; ++q) {
            const float4 iv = *(const float4*)&colp[lb0 + HALO - 8 + 4 * q];
            s  = fadd1(iv.x, fadd1(iv.y, fadd1(iv.z, fadd1(iv.w, s))));
            s2 = fmaf(iv.x, iv.x, s2);
            s2 = fmaf(iv.y, iv.y, s2);
            s2 = fmaf(iv.z, iv.z, s2);
            s2 = fmaf(iv.w, iv.w, s2);
        }
    } else {
        #pragma unroll
        for (int u = -8; u <= 7; ++u) {
            int g = tb0 + u;
            g = (g < 0)  ? -g              : g;
            g = (g >= T) ? (2 * T - 2 - g) : g;
            float w = colp[g - t0 + HALO];
            s  = fadd1(w, s);
            s2 = fmaf(w, w, s2);
        }
    }

    #pragma unroll 1
    for (int chunk = 0; chunk < TT / (NTY * RCHUNK); ++chunk) {   // 8 iterations
        const int lb = lb0 + chunk * RCHUNK;   // local first output row
        const int tb = t0 + lb;                // global first output row
        const int b0 = lb + HALO;              // tile row of output 0 (b0 % 4 == 0)

        // center taps (also xv): rows b0..b0+3, 16B aligned
        const float4 cq = *(const float4*)&colp[b0];
        const float cqa[4] = {cq.x, cq.y, cq.z, cq.w};

        // ---------- phase 1: carried mean / var (float4 adds/removes) ----------
        float m[RCHUNK], va[RCHUNK];
        if (interior) {
            const float4 aq = *(const float4*)&colp[b0 + 8];   // rows b0+8..b0+11
            const float4 rq = *(const float4*)&colp[b0 - 8];   // rows b0-8..b0-5
            const float wa4[4] = {aq.x, aq.y, aq.z, aq.w};
            const float wr4[4] = {rq.x, rq.y, rq.z, rq.w};
            #pragma unroll
            for (int i = 0; i < RCHUNK; ++i) {
                float wa = wa4[i], wr = wr4[i];
                s  = fadd1(wa, fnma1(wr, s));
                s2 = fmaf(wa, wa, s2);
                s2 = fmaf(wr, -wr, s2);
                float mm  = fmaf(s,  1.0f / 16.0f, 0.0f);
                float m2v = fmaf(s2, 1.0f / 16.0f, 0.0f);
                m[i]  = mm;
                va[i] = fmaxf(fmaf(-mm, mm, m2v), 0.0f);
            }
        } else {
            #pragma unroll
            for (int i = 0; i < RCHUNK; ++i) {
                int ga = tb + i + 8;  ga = (ga >= T) ? (2 * T - 2 - ga) : ga;
                int gr = tb + i - 8;  gr = (gr < 0)  ? -gr              : gr;
                float wa = colp[ga - t0 + HALO];
                float wr = colp[gr - t0 + HALO];
                s  = fadd1(wa, fnma1(wr, s));
                s2 = fmaf(wa, wa, s2);
                s2 = fmaf(wr, -wr, s2);
                float mm  = fmaf(s,  1.0f / 16.0f, 0.0f);
                float m2v = fmaf(s2, 1.0f / 16.0f, 0.0f);
                m[i]  = mm;
                va[i] = fmaxf(fmaf(-mm, mm, m2v), 0.0f);
            }
        }

        // pack features into f32x2 pairs (i, i+1)
        ull m2[2], v2p[2], x2[2];
        #pragma unroll
        for (int p = 0; p < 2; ++p) {
            m2[p]  = pk2(m[2 * p],  m[2 * p + 1]);
            v2p[p] = pk2(va[2 * p], va[2 * p + 1]);
            x2[p]  = pk2(cqa[2 * p], cqa[2 * p + 1]);
        }

        // ---------- phase 2: conditioner MLP, packed tanh.approx GELU ----------
        ull lg[2][4];
        #pragma unroll
        for (int p = 0; p < 2; ++p)
            #pragma unroll
            for (int k = 0; k < 4; ++k) lg[p][k] = wp[256 + k];   // b2d pairs

        #pragma unroll 4
        for (int j = 0; j < 32; ++j) {
            // 4 broadcast LDS.128: whole j-block (8 weight pairs) in 4 wavefronts
            const ull* wj = wp + 8 * j;
            ull w1m = wj[0], w1v = wj[1], w1x = wj[2], bj = wj[3];
            ull w20 = wj[4], w21 = wj[5], w22 = wj[6], w23 = wj[7];
            #pragma unroll
            for (int p = 0; p < 2; ++p) {
                ull z  = ffma2(m2[p], w1m, ffma2(v2p[p], w1v, ffma2(x2[p], w1x, bj)));
                ull zz = fmul2(z, z);
                ull u  = fmul2(z, ffma2(zz, CK2, CK1));
                float ul, uh; upk2(u, ul, uh);
                ull th = pk2(tanhf_a(ul), tanhf_a(uh));
                ull g  = ffma2(z, th, z);        // g' = z*(1 + tanh(u)) = 2*gelu
                lg[p][0] = ffma2(g, w20, lg[p][0]);
                lg[p][1] = ffma2(g, w21, lg[p][1]);
                lg[p][2] = ffma2(g, w22, lg[p][2]);
                lg[p][3] = ffma2(g, w23, lg[p][3]);
            }
        }

        // logits -> unnormalized softmax weights (e4 == 1), frees lg
        float ew[RCHUNK][4];
        #pragma unroll
        for (int p = 0; p < 2; ++p) {
            float lo, hi;
            #pragma unroll
            for (int k = 0; k < 4; ++k) {
                upk2(lg[p][k], lo, hi);
                ew[2 * p][k]     = ex2f(lo);
                ew[2 * p + 1][k] = ex2f(hi);
            }
        }

        // ---------- phase 3: symmetric conv, float4-streamed columns ----------
        float Y[RCHUNK][5];
        #pragma unroll
        for (int o = 0; o < RCHUNK; ++o)
            #pragma unroll
            for (int k = 0; k < 5; ++k) Y[o][k] = fmaf(cqa[o], BANK.w[k][56], 0.0f);

        float Lp[4] = {cqa[0], cqa[1], cqa[2], cqa[3]};  // rows b0..b0+3
        float Rp[4] = {cqa[0], cqa[1], cqa[2], cqa[3]};  // rows b0..b0+3
        #pragma unroll
        for (int g14 = 0; g14 < 14; ++g14) {
            const float4 lq = *(const float4*)&colp[b0 - 4 * g14 - 4];
            const float4 rq = *(const float4*)&colp[b0 + 4 * g14 + 4];
            const float Lc[4] = {lq.x, lq.y, lq.z, lq.w};
            const float Rc[4] = {rq.x, rq.y, rq.z, rq.w};
            #pragma unroll
            for (int dd = 1; dd <= 4; ++dd) {
                const int d = 4 * g14 + dd;
                #pragma unroll
                for (int o = 0; o < RCHUNK; ++o) {
                    const int el = 4 - dd + o;          // L row b0-d+o
                    const int er = dd + o;              // R row b0+d+o
                    float Lv = (el < 4) ? Lc[el] : Lp[el - 4];
                    float Rv = (er < 4) ? Rp[er] : Rc[er - 4];
                    if (d > RAD[3]) {
                        // single sigma tail: 2 FFMA-imm
                        Y[o][4] = fmaf(Lv, BANK.w[4][56 + d], Y[o][4]);
                        Y[o][4] = fmaf(Rv, BANK.w[4][56 + d], Y[o][4]);
                    } else {
                        float sv = fadd1(Lv, Rv);       // FFMA-imm
                        #pragma unroll
                        for (int k = 0; k < 5; ++k) {
                            if (d <= RAD[k])
                                Y[o][k] = fmaf(sv, BANK.w[k][56 + d], Y[o][k]);
                        }
                    }
                }
            }
            #pragma unroll
            for (int e = 0; e < 4; ++e) { Lp[e] = Lc[e]; Rp[e] = Rc[e]; }
        }

        // ---------- phase 4: softmax (e4 = 1) + mix + store ----------
        float* op = out + ((size_t)bb * T + tb) * C + c0 + tx;
        const float one = 1.0f;
        #pragma unroll
        for (int o = 0; o < RCHUNK; ++o) {
            float e0 = ew[o][0], e1 = ew[o][1], e2 = ew[o][2], e3 = ew[o][3];
            float sum = fadd1(e0, fadd1(e1, fadd1(e2, fadd1(e3, one))));
            float dot = fmaf(e0, Y[o][0], Y[o][4]);
            dot = fmaf(e1, Y[o][1], dot);
            dot = fmaf(e2, Y[o][2], dot);
            dot = fmaf(e3, Y[o][3], dot);
            op[(size_t)o * C] = dot * rcpf(sum);
        }
    }
}

// ---------------- launch ----------------
extern "C" void kernel_launch(void* const* d_in, const int* in_sizes, int n_in,
                              void* d_out, int out_size) {
    const float* x  = (const float*)d_in[0];
    const float* W1 = (const float*)d_in[1];
    const float* b1 = (const float*)d_in[2];
    const float* W2 = (const float*)d_in[3];
    const float* b2 = (const float*)d_in[4];
    float* out = (float*)d_out;

    const int B = 16, T = 4096, C = 256;
    size_t smem = (size_t)(WSF + 576) * sizeof(float);
    cudaFuncSetAttribute(agt_kernel, cudaFuncAttributeMaxDynamicSharedMemorySize, (int)smem);

    dim3 grid(C / CT, T / TT, B);
    dim3 block(CT, NTY);
    agt_kernel<<<grid, block, smem>>>(x, W1, b1, W2, b2, out, B, T, C);
}